// round 15
// baseline (speedup 1.0000x reference)
#include <cuda_runtime.h>
#include <cuda_bf16.h>
#include <cstdint>
#include <cstddef>

// ============================================================================
// out[4096,4096](fp32, bf16-valued) = bf16(X[4096,4096]) @ (bf16(Wq)*bf16(s))^T
// Single fused kernel: fp32 LDG -> bf16 convert in regs -> STS (padded smem)
// -> ldmatrix -> mma.sync.m16n8k16.bf16 (rt~16/SMSP: the sm_103 legacy-HMMA
// floor). 3-stage smem ring, one barrier per stage. No scratch pass.
// ============================================================================
#define MDIM 4096
#define NDIM 4096
#define KDIM 4096

#define BM 128
#define BN 128
#define BK 64                 // 64 bf16 = 128 B of K per stage row
#define STAGES 3
#define THREADS 512

#define AST 144               // padded row stride (128 data + 16 pad)
#define A_STAGE (BM * AST)                    // 18432 B
#define B_STAGE (BN * AST)                    // 18432 B
#define STAGE_BYTES (A_STAGE + B_STAGE)       // 36864 B
#define SMEM_BYTES (STAGES * STAGE_BYTES + 256)   // ~110.8 KB

#define NUM_K_ITERS (KDIM / BK)   // 64
#define NUM_M_TILES (MDIM / BM)   // 32
#define NUM_N_TILES (NDIM / BN)   // 32

// ============================================================================
// PTX helpers
// ============================================================================
__device__ __forceinline__ uint32_t smem_u32(const void* p) {
    uint32_t a;
    asm("{ .reg .u64 t; cvta.to.shared.u64 t, %1; cvt.u32.u64 %0, t; }"
        : "=r"(a) : "l"(p));
    return a;
}

__device__ __forceinline__ void ldsm_x4(uint32_t& r0, uint32_t& r1,
                                        uint32_t& r2, uint32_t& r3,
                                        uint32_t addr) {
    asm volatile("ldmatrix.sync.aligned.m8n8.x4.shared.b16 {%0,%1,%2,%3}, [%4];"
                 : "=r"(r0), "=r"(r1), "=r"(r2), "=r"(r3) : "r"(addr));
}

__device__ __forceinline__ void mma16816(float* c, const uint32_t* a,
                                         uint32_t b0, uint32_t b1) {
    asm volatile(
        "mma.sync.aligned.m16n8k16.row.col.f32.bf16.bf16.f32 "
        "{%0,%1,%2,%3}, {%4,%5,%6,%7}, {%8,%9}, {%0,%1,%2,%3};"
        : "+f"(c[0]), "+f"(c[1]), "+f"(c[2]), "+f"(c[3])
        : "r"(a[0]), "r"(a[1]), "r"(a[2]), "r"(a[3]), "r"(b0), "r"(b1));
}

__device__ __forceinline__ unsigned pack2(__nv_bfloat16 lo, __nv_bfloat16 hi) {
    return (unsigned)__bfloat16_as_ushort(lo) |
           ((unsigned)__bfloat16_as_ushort(hi) << 16);
}

// Pack 4 fp32 -> 2 bf16x2 words (plain cast, X path)
__device__ __forceinline__ void cvt4(const float4& f, unsigned& u0, unsigned& u1) {
    u0 = pack2(__float2bfloat16_rn(f.x), __float2bfloat16_rn(f.y));
    u1 = pack2(__float2bfloat16_rn(f.z), __float2bfloat16_rn(f.w));
}

// Pack 4 fp32 -> 2 bf16x2 words with bf16 scale multiply (W dequant path),
// matching jnp: bf16(w_fp8) * bf16(scale)
__device__ __forceinline__ void cvt4s(const float4& f, __nv_bfloat16 s,
                                      unsigned& u0, unsigned& u1) {
    u0 = pack2(__hmul(__float2bfloat16_rn(f.x), s),
               __hmul(__float2bfloat16_rn(f.y), s));
    u1 = pack2(__hmul(__float2bfloat16_rn(f.z), s),
               __hmul(__float2bfloat16_rn(f.w), s));
}

// ============================================================================
// Fused GEMM: 128x128x64 CTA tile, 16 warps @ 32x32, 3-stage STS pipeline
// ============================================================================
__global__ __launch_bounds__(THREADS, 1) void gemm_kernel(
    float* __restrict__ out,
    const float* __restrict__ x,
    const float* __restrict__ w,
    const float* __restrict__ scale,
    const float* __restrict__ bias) {
    extern __shared__ char smem[];
    const uint32_t sraw = smem_u32(smem);
    const uint32_t base = (sraw + 127u) & ~127u;
    char* smp = smem + (base - sraw);          // 128-aligned char* mirror

    const int tid = threadIdx.x;
    const int lane = tid & 31;
    const int wid = tid >> 5;
    const int wm0 = (wid & 3) * 32;    // 4 warp rows * 32 = 128
    const int wn0 = (wid >> 2) * 32;   // 4 warp cols * 32 = 128

    const int bid = blockIdx.x;
    const int tm = bid & (NUM_M_TILES - 1);  // consecutive bids share W panel
    const int tn = bid >> 5;
    const int m0 = tm * BM;
    const int n0 = tn * BN;

    // Producer coordinates: each thread owns 2 A-chunks + 2 B-chunks (16B bf16
    // each) per stage; source = 2 float4 fp32 per chunk.
    const int ld_r = tid >> 3;        // 0..63
    const int ld_c = tid & 7;         // 0..7

    const float* Axf = x + (size_t)(m0 + ld_r) * KDIM + ld_c * 8;
    const float* Bwf = w + (size_t)(n0 + ld_r) * KDIM + ld_c * 8;

    // Per-thread W row scales (rows ld_r, ld_r+64 of this N panel)
    const __nv_bfloat16 sc0 = __float2bfloat16_rn(scale[n0 + ld_r]);
    const __nv_bfloat16 sc1 = __float2bfloat16_rn(scale[n0 + ld_r + 64]);

    float4 ra[2][2], rb[2][2];         // one stage in flight (32 regs)

    auto ldg_stage = [&](int kit) {
        if (kit < NUM_K_ITERS) {
            const float4* a0 = reinterpret_cast<const float4*>(Axf + kit * BK);
            const float4* a1 = reinterpret_cast<const float4*>(Axf + kit * BK +
                                                               (size_t)64 * KDIM);
            const float4* b0 = reinterpret_cast<const float4*>(Bwf + kit * BK);
            const float4* b1 = reinterpret_cast<const float4*>(Bwf + kit * BK +
                                                               (size_t)64 * KDIM);
            ra[0][0] = a0[0]; ra[0][1] = a0[1];
            ra[1][0] = a1[0]; ra[1][1] = a1[1];
            rb[0][0] = b0[0]; rb[0][1] = b0[1];
            rb[1][0] = b1[0]; rb[1][1] = b1[1];
        }
    };

    auto sts_stage = [&](int kit) {
        if (kit < NUM_K_ITERS) {
            const int s = kit % STAGES;
            char* sa = smp + s * STAGE_BYTES + ld_r * AST + ld_c * 16;
            char* sb = sa + A_STAGE;
            uint4 u;
            cvt4(ra[0][0], u.x, u.y); cvt4(ra[0][1], u.z, u.w);
            *reinterpret_cast<uint4*>(sa) = u;
            cvt4(ra[1][0], u.x, u.y); cvt4(ra[1][1], u.z, u.w);
            *reinterpret_cast<uint4*>(sa + 64 * AST) = u;
            cvt4s(rb[0][0], sc0, u.x, u.y); cvt4s(rb[0][1], sc0, u.z, u.w);
            *reinterpret_cast<uint4*>(sb) = u;
            cvt4s(rb[1][0], sc1, u.x, u.y); cvt4s(rb[1][1], sc1, u.z, u.w);
            *reinterpret_cast<uint4*>(sb + 64 * AST) = u;
        }
    };

    // ldmatrix x4: lane 8i+j supplies row j of matrix i.
    const int g = lane >> 3;
    const int j = lane & 7;
    const int frag_row = (g & 1) * 8 + j;           // 0..15
    const int frag_kb  = (g >> 1) * 16;             // 0 or 16 bytes

    const uint32_t a_off0 = (uint32_t)((wm0 + frag_row) * AST + frag_kb);
    const uint32_t b_off0 = (uint32_t)((wn0 + frag_row) * AST + frag_kb);

    float acc[2][4][4];                // 32x32 warp tile = 32 regs
#pragma unroll
    for (int i = 0; i < 2; i++)
#pragma unroll
        for (int n = 0; n < 4; n++)
#pragma unroll
            for (int e = 0; e < 4; e++) acc[i][n][e] = 0.0f;

    // Prologue: stage 0 into smem, stage 1 into regs
    ldg_stage(0);
    sts_stage(0);
    ldg_stage(1);

    for (int kit = 0; kit < NUM_K_ITERS; kit++) {
        const int s = kit % STAGES;
        __syncthreads();       // STS(kit) from iter kit-1 visible; slot protect

        sts_stage(kit + 1);    // regs -> slot (kit+1)%3 (last read iter kit-2)
        ldg_stage(kit + 2);    // refill regs; consumed next iteration

        const uint32_t sa = base + s * STAGE_BYTES;
        const uint32_t sb = sa + A_STAGE;

#pragma unroll
        for (int q = 0; q < 4; q++) {              // 4 x K16 per BK=64 stage
            const uint32_t kb = (uint32_t)(q * 32);
            uint32_t a[2][4], b[2][4];
#pragma unroll
            for (int mi = 0; mi < 2; mi++)
                ldsm_x4(a[mi][0], a[mi][1], a[mi][2], a[mi][3],
                        sa + a_off0 + mi * 16 * AST + kb);
#pragma unroll
            for (int p = 0; p < 2; p++)
                ldsm_x4(b[p][0], b[p][1], b[p][2], b[p][3],
                        sb + b_off0 + p * 16 * AST + kb);
#pragma unroll
            for (int p = 0; p < 2; p++)
#pragma unroll
                for (int mi = 0; mi < 2; mi++) {
                    mma16816(acc[mi][2 * p],     a[mi], b[p][0], b[p][2]);
                    mma16816(acc[mi][2 * p + 1], a[mi], b[p][1], b[p][3]);
                }
        }
    }

    // Epilogue: value = bf16(fp32 accum) + bf16 bias, stored as fp32
#pragma unroll
    for (int mi = 0; mi < 2; mi++) {
        int r0 = m0 + wm0 + mi * 16 + (lane >> 2);
        float* p0 = out + (size_t)r0 * NDIM;
        float* p1 = p0 + (size_t)8 * NDIM;
#pragma unroll
        for (int nj = 0; nj < 4; nj++) {
            int col = n0 + wn0 + nj * 8 + (lane & 3) * 2;
            __nv_bfloat16 b0 = __float2bfloat16_rn(bias[col]);
            __nv_bfloat16 b1 = __float2bfloat16_rn(bias[col + 1]);
            float2 v0, v1;
            v0.x = __bfloat162float(__hadd(__float2bfloat16_rn(acc[mi][nj][0]), b0));
            v0.y = __bfloat162float(__hadd(__float2bfloat16_rn(acc[mi][nj][1]), b1));
            v1.x = __bfloat162float(__hadd(__float2bfloat16_rn(acc[mi][nj][2]), b0));
            v1.y = __bfloat162float(__hadd(__float2bfloat16_rn(acc[mi][nj][3]), b1));
            *reinterpret_cast<float2*>(p0 + col) = v0;
            *reinterpret_cast<float2*>(p1 + col) = v1;
        }
    }
}

// ============================================================================
// Launch
// ============================================================================
extern "C" void kernel_launch(void* const* d_in, const int* in_sizes, int n_in,
                              void* d_out, int out_size) {
    const float* x     = (const float*)d_in[0];
    const float* wq    = (const float*)d_in[1];
    const float* wscal = (const float*)d_in[2];
    const float* bias  = (const float*)d_in[3];
    float* out         = (float*)d_out;

    cudaFuncSetAttribute(gemm_kernel,
                         cudaFuncAttributeMaxDynamicSharedMemorySize,
                         SMEM_BYTES);

    gemm_kernel<<<NUM_M_TILES * NUM_N_TILES, THREADS, SMEM_BYTES>>>(
        out, x, wq, wscal, bias);
}

// round 16
// speedup vs baseline: 1.7097x; 1.7097x over previous
#include <cuda_runtime.h>
#include <cuda_bf16.h>
#include <cstdint>
#include <cstddef>

// ============================================================================
// out[4096,4096](fp32, bf16-valued) = X[4096,4096](bf16) @ W[4096,4096]^T
// Split converts (roofline-bound, ~28us) + mma.sync bf16 GEMM at the legacy-
// HMMA ceiling. This round: 2 CTAs/SM (256 thr, BM=BN=128, 3-stage cp.async)
// so barrier bubbles / epilogues of one CTA hide under the other's MMAs.
// ============================================================================
#define MDIM 4096
#define NDIM 4096
#define KDIM 4096

#define BM 128
#define BN 128
#define BK 64                 // 64 bf16 = 128 B of K per stage row
#define STAGES 3
#define THREADS 256

#define AST 144               // padded row stride (128 data + 16 pad)
#define A_STAGE (BM * AST)                    // 18432 B
#define B_STAGE (BN * AST)                    // 18432 B
#define STAGE_BYTES (A_STAGE + B_STAGE)       // 36864 B
#define SMEM_BYTES (STAGES * STAGE_BYTES + 128)   // ~110.7 KB (2 CTAs/SM)

#define NUM_K_ITERS (KDIM / BK)   // 64
#define NUM_M_TILES (MDIM / BM)   // 32
#define NUM_N_TILES (NDIM / BN)   // 32

__device__ __nv_bfloat16 g_xb[(size_t)MDIM * KDIM];
__device__ __nv_bfloat16 g_wb[(size_t)NDIM * KDIM];

// ============================================================================
// PTX helpers
// ============================================================================
__device__ __forceinline__ uint32_t smem_u32(const void* p) {
    uint32_t a;
    asm("{ .reg .u64 t; cvta.to.shared.u64 t, %1; cvt.u32.u64 %0, t; }"
        : "=r"(a) : "l"(p));
    return a;
}

__device__ __forceinline__ void cp_async16(uint32_t dst, const void* src) {
    asm volatile("cp.async.cg.shared.global [%0], [%1], 16;"
                 :: "r"(dst), "l"(src) : "memory");
}

__device__ __forceinline__ void cp_commit() {
    asm volatile("cp.async.commit_group;" ::: "memory");
}

template <int N>
__device__ __forceinline__ void cp_wait() {
    asm volatile("cp.async.wait_group %0;" :: "n"(N) : "memory");
}

__device__ __forceinline__ void ldsm_x4(uint32_t& r0, uint32_t& r1,
                                        uint32_t& r2, uint32_t& r3,
                                        uint32_t addr) {
    asm volatile("ldmatrix.sync.aligned.m8n8.x4.shared.b16 {%0,%1,%2,%3}, [%4];"
                 : "=r"(r0), "=r"(r1), "=r"(r2), "=r"(r3) : "r"(addr));
}

__device__ __forceinline__ void mma16816(float* c, const uint32_t* a,
                                         uint32_t b0, uint32_t b1) {
    asm volatile(
        "mma.sync.aligned.m16n8k16.row.col.f32.bf16.bf16.f32 "
        "{%0,%1,%2,%3}, {%4,%5,%6,%7}, {%8,%9}, {%0,%1,%2,%3};"
        : "+f"(c[0]), "+f"(c[1]), "+f"(c[2]), "+f"(c[3])
        : "r"(a[0]), "r"(a[1]), "r"(a[2]), "r"(a[3]), "r"(b0), "r"(b1));
}

__device__ __forceinline__ unsigned pack2(__nv_bfloat16 lo, __nv_bfloat16 hi) {
    return (unsigned)__bfloat16_as_ushort(lo) |
           ((unsigned)__bfloat16_as_ushort(hi) << 16);
}

// ============================================================================
// Fused convert: blocks [0,8192) cast X; [8192,16384) dequant W (bf16 math)
// ============================================================================
__global__ __launch_bounds__(256) void cvt_kernel(const float* __restrict__ x,
                                                  const float* __restrict__ w,
                                                  const float* __restrict__ scale) {
    if (blockIdx.x < 8192) {
        size_t i = (size_t)blockIdx.x * 256 + threadIdx.x;      // 8 floats
        const float4* p = reinterpret_cast<const float4*>(x) + i * 2;
        float4 a = p[0], b = p[1];
        uint4 o;
        o.x = pack2(__float2bfloat16_rn(a.x), __float2bfloat16_rn(a.y));
        o.y = pack2(__float2bfloat16_rn(a.z), __float2bfloat16_rn(a.w));
        o.z = pack2(__float2bfloat16_rn(b.x), __float2bfloat16_rn(b.y));
        o.w = pack2(__float2bfloat16_rn(b.z), __float2bfloat16_rn(b.w));
        reinterpret_cast<uint4*>(g_xb)[i] = o;
    } else {
        size_t i = (size_t)(blockIdx.x - 8192) * 256 + threadIdx.x;
        int row = (int)(i >> 9);
        __nv_bfloat16 sb = __float2bfloat16_rn(scale[row]);
        const float4* p = reinterpret_cast<const float4*>(w) + i * 2;
        float4 a = p[0], b = p[1];
        float f[8] = {a.x, a.y, a.z, a.w, b.x, b.y, b.z, b.w};
        unsigned u[4];
#pragma unroll
        for (int j = 0; j < 4; j++) {
            __nv_bfloat16 lo = __hmul(__float2bfloat16_rn(f[2 * j]), sb);
            __nv_bfloat16 hi = __hmul(__float2bfloat16_rn(f[2 * j + 1]), sb);
            u[j] = pack2(lo, hi);
        }
        reinterpret_cast<uint4*>(g_wb)[i] = make_uint4(u[0], u[1], u[2], u[3]);
    }
}

// ============================================================================
// GEMM: 128x128x64 CTA tile, 8 warps @ 32x64, 3-stage pipeline, 2 CTAs/SM
// ============================================================================
__global__ __launch_bounds__(THREADS, 2) void gemm_kernel(
    float* __restrict__ out, const float* __restrict__ bias) {
    extern __shared__ char smem[];
    const uint32_t base = (smem_u32(smem) + 127u) & ~127u;

    const int tid = threadIdx.x;
    const int lane = tid & 31;
    const int wid = tid >> 5;
    const int wm0 = (wid & 3) * 32;    // 4 warp rows * 32 = 128
    const int wn0 = (wid >> 2) * 64;   // 2 warp cols * 64 = 128

    const int bid = blockIdx.x;
    const int tm = bid & (NUM_M_TILES - 1);  // consecutive bids share W panel
    const int tn = bid >> 5;
    const int m0 = tm * BM;
    const int n0 = tn * BN;

    const __nv_bfloat16* Ag = g_xb + (size_t)m0 * KDIM;
    const __nv_bfloat16* Bg = g_wb + (size_t)n0 * KDIM;

    // cp.async: 256 threads; A+B = 2048 16B chunks per stage -> 8/thread
    const int ld_r = tid >> 3;        // 0..31
    const int ld_c = tid & 7;         // 0..7

    auto load_stage = [&](int kit, int s) {
        if (kit < NUM_K_ITERS) {
            const uint32_t sa = base + s * STAGE_BYTES;
            const uint32_t sb = sa + A_STAGE;
            const __nv_bfloat16* ak = Ag + kit * BK + ld_c * 8;
            const __nv_bfloat16* bk = Bg + kit * BK + ld_c * 8;
#pragma unroll
            for (int it = 0; it < 4; it++) {       // A: 128 rows
                int r = ld_r + it * 32;
                cp_async16(sa + r * AST + ld_c * 16, ak + (size_t)r * KDIM);
            }
#pragma unroll
            for (int it = 0; it < 4; it++) {       // B: 128 rows
                int r = ld_r + it * 32;
                cp_async16(sb + r * AST + ld_c * 16, bk + (size_t)r * KDIM);
            }
        }
        cp_commit();
    };

    // ldmatrix x4: lane 8i+j supplies row j of matrix i.
    const int g = lane >> 3;
    const int j = lane & 7;
    const int frag_row = (g & 1) * 8 + j;           // 0..15
    const int frag_kb  = (g >> 1) * 16;             // 0 or 16 bytes

    const uint32_t a_off0 = (uint32_t)((wm0 + frag_row) * AST + frag_kb);
    const uint32_t b_off0 = (uint32_t)((wn0 + frag_row) * AST + frag_kb);

    float acc[2][8][4];                // 32x64 warp tile = 64 regs
#pragma unroll
    for (int i = 0; i < 2; i++)
#pragma unroll
        for (int n = 0; n < 8; n++)
#pragma unroll
            for (int e = 0; e < 4; e++) acc[i][n][e] = 0.0f;

    // Prologue: fill STAGES-1 = 2 stages (prefetch distance 2)
    load_stage(0, 0);
    load_stage(1, 1);

    for (int kit = 0; kit < NUM_K_ITERS; kit++) {
        const int s = kit % STAGES;
        cp_wait<1>();          // stage kit's group complete
        __syncthreads();       // single barrier per stage

        // Prefetch stage kit+2 into slot (kit+2)%3 = (kit-1)%3, whose reads
        // completed during iteration kit-1 (before this barrier).
        load_stage(kit + 2, (kit + 2) % STAGES);

        const uint32_t sa = base + s * STAGE_BYTES;
        const uint32_t sb = sa + A_STAGE;

#pragma unroll
        for (int q = 0; q < 4; q++) {              // 4 x K16 per BK=64 stage
            const uint32_t kb = (uint32_t)(q * 32);
            uint32_t a[2][4], b[4][4];
#pragma unroll
            for (int mi = 0; mi < 2; mi++)
                ldsm_x4(a[mi][0], a[mi][1], a[mi][2], a[mi][3],
                        sa + a_off0 + mi * 16 * AST + kb);
#pragma unroll
            for (int p = 0; p < 4; p++)
                ldsm_x4(b[p][0], b[p][1], b[p][2], b[p][3],
                        sb + b_off0 + p * 16 * AST + kb);
#pragma unroll
            for (int p = 0; p < 4; p++)
#pragma unroll
                for (int mi = 0; mi < 2; mi++) {
                    mma16816(acc[mi][2 * p],     a[mi], b[p][0], b[p][2]);
                    mma16816(acc[mi][2 * p + 1], a[mi], b[p][1], b[p][3]);
                }
        }
    }

    // Epilogue: value = bf16(fp32 accum) + bf16 bias, stored as fp32
#pragma unroll
    for (int mi = 0; mi < 2; mi++) {
        int r0 = m0 + wm0 + mi * 16 + (lane >> 2);
        float* p0 = out + (size_t)r0 * NDIM;
        float* p1 = p0 + (size_t)8 * NDIM;
#pragma unroll
        for (int nj = 0; nj < 8; nj++) {
            int col = n0 + wn0 + nj * 8 + (lane & 3) * 2;
            __nv_bfloat16 b0 = __float2bfloat16_rn(bias[col]);
            __nv_bfloat16 b1 = __float2bfloat16_rn(bias[col + 1]);
            float2 v0, v1;
            v0.x = __bfloat162float(__hadd(__float2bfloat16_rn(acc[mi][nj][0]), b0));
            v0.y = __bfloat162float(__hadd(__float2bfloat16_rn(acc[mi][nj][1]), b1));
            v1.x = __bfloat162float(__hadd(__float2bfloat16_rn(acc[mi][nj][2]), b0));
            v1.y = __bfloat162float(__hadd(__float2bfloat16_rn(acc[mi][nj][3]), b1));
            *reinterpret_cast<float2*>(p0 + col) = v0;
            *reinterpret_cast<float2*>(p1 + col) = v1;
        }
    }
}

// ============================================================================
// Launch
// ============================================================================
extern "C" void kernel_launch(void* const* d_in, const int* in_sizes, int n_in,
                              void* d_out, int out_size) {
    const float* x     = (const float*)d_in[0];
    const float* wq    = (const float*)d_in[1];
    const float* wscal = (const float*)d_in[2];
    const float* bias  = (const float*)d_in[3];
    float* out         = (float*)d_out;

    cudaFuncSetAttribute(gemm_kernel,
                         cudaFuncAttributeMaxDynamicSharedMemorySize,
                         SMEM_BYTES);

    cvt_kernel<<<16384, 256>>>(x, wq, wscal);
    gemm_kernel<<<NUM_M_TILES * NUM_N_TILES, THREADS, SMEM_BYTES>>>(out, bias);
}